// round 2
// baseline (speedup 1.0000x reference)
#include <cuda_runtime.h>
#include <cuda_bf16.h>
#include <math.h>

// Problem constants
#define BATCH 2
#define SEQ   2048
#define EMB   512
#define HEADS 8
#define HDIM  64
#define MROWS (BATCH * SEQ)   // 4096

// ---------------------------------------------------------------------------
// Scratch (device globals; allocation inside kernel_launch is forbidden)
// ---------------------------------------------------------------------------
__device__ float g_Q [MROWS * EMB];
__device__ float g_K [MROWS * EMB];
__device__ float g_V [MROWS * EMB];
__device__ float g_G [MROWS * EMB];
__device__ float g_X2[MROWS * EMB];

// ---------------------------------------------------------------------------
// Generic GEMM: C[M=4096, N=512] = A[M,512] @ W[N,512]^T + bias
// MODE 0: plain   MODE 1: silu   MODE 2: rotary(q)   MODE 3: rotary(k)*1/8
// Block tile 128x128, K-tile 8, 256 threads, 8x8 micro-tile with stride-16
// column/row mapping (rotary pair partner lives in the adjacent lane -> shfl).
// ---------------------------------------------------------------------------
template <int MODE>
__global__ void __launch_bounds__(256)
gemm_k(const float* __restrict__ A, const float* __restrict__ W,
       const float* __restrict__ bias, float* __restrict__ C)
{
    __shared__ float As[8][128];
    __shared__ float Bs[8][128];

    const int tx = threadIdx.x & 15;
    const int ty = threadIdx.x >> 4;
    const int mBase = blockIdx.y * 128;
    const int nBase = blockIdx.x * 128;

    const int lrow  = threadIdx.x >> 1;        // 0..127
    const int lhalf = (threadIdx.x & 1) * 4;   // 0 or 4

    const float* Aptr = A + (size_t)(mBase + lrow) * EMB + lhalf;
    const float* Wptr = W + (size_t)(nBase + lrow) * EMB + lhalf;

    float acc[8][8];
#pragma unroll
    for (int i = 0; i < 8; i++)
#pragma unroll
        for (int j = 0; j < 8; j++) acc[i][j] = 0.f;

    for (int k0 = 0; k0 < EMB; k0 += 8) {
        float4 av = *(const float4*)(Aptr + k0);
        float4 wv = *(const float4*)(Wptr + k0);
        __syncthreads();   // previous compute done before overwrite
        As[lhalf + 0][lrow] = av.x;
        As[lhalf + 1][lrow] = av.y;
        As[lhalf + 2][lrow] = av.z;
        As[lhalf + 3][lrow] = av.w;
        Bs[lhalf + 0][lrow] = wv.x;
        Bs[lhalf + 1][lrow] = wv.y;
        Bs[lhalf + 2][lrow] = wv.z;
        Bs[lhalf + 3][lrow] = wv.w;
        __syncthreads();
#pragma unroll
        for (int kk = 0; kk < 8; kk++) {
            float ra[8], rb[8];
#pragma unroll
            for (int ii = 0; ii < 8; ii++) ra[ii] = As[kk][ty + ii * 16];
#pragma unroll
            for (int jj = 0; jj < 8; jj++) rb[jj] = Bs[kk][tx + jj * 16];
#pragma unroll
            for (int ii = 0; ii < 8; ii++)
#pragma unroll
                for (int jj = 0; jj < 8; jj++)
                    acc[ii][jj] = fmaf(ra[ii], rb[jj], acc[ii][jj]);
        }
    }

    // Epilogue
#pragma unroll
    for (int ii = 0; ii < 8; ii++) {
        const int m = mBase + ty + ii * 16;
        const int n_seq = m & (SEQ - 1);
#pragma unroll
        for (int jj = 0; jj < 8; jj++) {
            const int c = nBase + tx + jj * 16;
            float v = acc[ii][jj] + bias[c];
            float y;
            if (MODE == 0) {
                y = v;
            } else if (MODE == 1) {
                y = v / (1.f + expf(-v));     // silu
            } else {
                // rotary: pair partner is in lane ^ 1 (tx parity == col parity)
                float partner = __shfl_xor_sync(0xffffffffu, v, 1);
                const int d = c & (HDIM - 1);
                const int p = d >> 1;
                float theta = powf(10000.f, -(float)p * (1.0f / 31.0f));
                float ang = (float)n_seq * theta;
                float sv, cv;
                sincosf(ang, &sv, &cv);
                y = ((tx & 1) == 0) ? (v * cv - partner * sv)
                                    : (v * cv + partner * sv);
                if (MODE == 3) y *= 0.125f;   // 1/sqrt(HDIM)
            }
            C[(size_t)m * EMB + c] = y;
        }
    }
}

// ---------------------------------------------------------------------------
// Fused retention: per (b,h), ret = (Q K^T * decay) V, then GroupNorm over d
// and multiply by (pre-siluized) gate. Flash-style 64x64 tiles, no sim matrix.
// ---------------------------------------------------------------------------
#define RP_QK 65   // pad for Qs/Ks (bank-friendly strided reads)
#define RP_VS 68   // pad for Vs/Ss (float4-aligned rows)
#define RET_SMEM_FLOATS (64*RP_QK*2 + 64*RP_VS*2 + 128)

__global__ void __launch_bounds__(256)
retention_k(const float* __restrict__ Q, const float* __restrict__ K,
            const float* __restrict__ V, const float* __restrict__ G,
            float* __restrict__ O)
{
    extern __shared__ float sm[];
    float* Qs  = sm;                      // [64][65]
    float* Ks  = Qs + 64 * RP_QK;         // [64][65]
    float* Vs  = Ks + 64 * RP_QK;         // [64][68]
    float* Ss  = Vs + 64 * RP_VS;         // [64][68]
    float* tab = Ss + 64 * RP_VS;         // [127] gamma^(-63..63)

    const int tid = threadIdx.x;
    const int tx  = tid & 15;
    const int ty  = tid >> 4;
    const int bh  = blockIdx.y;
    const int b   = bh >> 3;
    const int h   = bh & 7;
    const int rowBase = blockIdx.x * 64;

    // gamma_h = 1 - exp(linspace(log(1/32), log(1/512), 8)[h])
    const double la = -3.4657359027997265;   // log(1/32)
    const double lb = -6.2383246250395075;   // log(1/512)
    const double lg = la + (lb - la) * ((double)h / 7.0);
    const float gamma = (float)(1.0 - exp(lg));
    const float lg2g  = log2f(gamma);

    for (int i = tid; i < 127; i += 256)
        tab[i] = exp2f(lg2g * (float)(i - 63));

    // load Q tile
    {
        const float* qb = Q + ((size_t)(b * SEQ + rowBase)) * EMB + h * HDIM;
        for (int e = tid; e < 64 * 16; e += 256) {
            int r  = e >> 4;
            int c4 = (e & 15) << 2;
            float4 v = *(const float4*)(qb + (size_t)r * EMB + c4);
            float* dst = &Qs[r * RP_QK + c4];
            dst[0] = v.x; dst[1] = v.y; dst[2] = v.z; dst[3] = v.w;
        }
    }

    float acc[4][4];
#pragma unroll
    for (int i = 0; i < 4; i++)
#pragma unroll
        for (int j = 0; j < 4; j++) acc[i][j] = 0.f;

    for (int sT = 0; sT <= (int)blockIdx.x; sT++) {
        const int colBase = sT * 64;
        const float* kb = K + ((size_t)(b * SEQ + colBase)) * EMB + h * HDIM;
        const float* vb = V + ((size_t)(b * SEQ + colBase)) * EMB + h * HDIM;

        __syncthreads();   // previous Ss/Vs consumption done
        for (int e = tid; e < 64 * 16; e += 256) {
            int r  = e >> 4;
            int c4 = (e & 15) << 2;
            float4 kv = *(const float4*)(kb + (size_t)r * EMB + c4);
            float4 vv = *(const float4*)(vb + (size_t)r * EMB + c4);
            float* kd = &Ks[r * RP_QK + c4];
            kd[0] = kv.x; kd[1] = kv.y; kd[2] = kv.z; kd[3] = kv.w;
            float* vd = &Vs[r * RP_VS + c4];
            vd[0] = vv.x; vd[1] = vv.y; vd[2] = vv.z; vd[3] = vv.w;
        }
        __syncthreads();

        const float basefac = exp2f(lg2g * (float)(rowBase - colBase));

        // S = Q K^T  (4x4 micro)
        float s[4][4];
#pragma unroll
        for (int i = 0; i < 4; i++)
#pragma unroll
            for (int j = 0; j < 4; j++) s[i][j] = 0.f;

#pragma unroll 4
        for (int d = 0; d < 64; d++) {
            float ra[4], rk[4];
#pragma unroll
            for (int ii = 0; ii < 4; ii++) ra[ii] = Qs[(ty * 4 + ii) * RP_QK + d];
#pragma unroll
            for (int jj = 0; jj < 4; jj++) rk[jj] = Ks[(tx * 4 + jj) * RP_QK + d];
#pragma unroll
            for (int ii = 0; ii < 4; ii++)
#pragma unroll
                for (int jj = 0; jj < 4; jj++)
                    s[ii][jj] = fmaf(ra[ii], rk[jj], s[ii][jj]);
        }

        // decay mask + stage to smem
#pragma unroll
        for (int ii = 0; ii < 4; ii++) {
            const int li = ty * 4 + ii;
            const int ig = rowBase + li;
#pragma unroll
            for (int jj = 0; jj < 4; jj++) {
                const int lj = tx * 4 + jj;
                const int jg = colBase + lj;
                float w = (jg <= ig) ? basefac * tab[li - lj + 63] : 0.f;
                Ss[li * RP_VS + lj] = s[ii][jj] * w;
            }
        }
        __syncthreads();

        // acc += S V
#pragma unroll 4
        for (int j = 0; j < 64; j++) {
            float rs[4];
#pragma unroll
            for (int ii = 0; ii < 4; ii++) rs[ii] = Ss[(ty * 4 + ii) * RP_VS + j];
            float4 rv = *(const float4*)&Vs[j * RP_VS + tx * 4];
#pragma unroll
            for (int ii = 0; ii < 4; ii++) {
                acc[ii][0] = fmaf(rs[ii], rv.x, acc[ii][0]);
                acc[ii][1] = fmaf(rs[ii], rv.y, acc[ii][1]);
                acc[ii][2] = fmaf(rs[ii], rv.z, acc[ii][2]);
                acc[ii][3] = fmaf(rs[ii], rv.w, acc[ii][3]);
            }
        }
    }

    // GroupNorm over d (per row) + gate multiply + store
#pragma unroll
    for (int ii = 0; ii < 4; ii++) {
        float s1 = 0.f, s2 = 0.f;
#pragma unroll
        for (int dd = 0; dd < 4; dd++) {
            s1 += acc[ii][dd];
            s2 += acc[ii][dd] * acc[ii][dd];
        }
        // reduce across the 16 tx lanes (lane = (ty&1)*16 + tx; xor<16 stays in group)
#pragma unroll
        for (int msk = 8; msk >= 1; msk >>= 1) {
            s1 += __shfl_xor_sync(0xffffffffu, s1, msk);
            s2 += __shfl_xor_sync(0xffffffffu, s2, msk);
        }
        const float mean = s1 * (1.f / 64.f);
        float var = s2 * (1.f / 64.f) - mean * mean;
        var = fmaxf(var, 0.f);
        const float inv = rsqrtf(var + 1e-6f);

        const int mrow = b * SEQ + rowBase + ty * 4 + ii;
        const float* gp = G + (size_t)mrow * EMB + h * HDIM + tx * 4;
        float*       op = O + (size_t)mrow * EMB + h * HDIM + tx * 4;
#pragma unroll
        for (int dd = 0; dd < 4; dd++) {
            float x = (acc[ii][dd] - mean) * inv;
            op[dd] = x * gp[dd];
        }
    }
}

// ---------------------------------------------------------------------------
// Launch
// ---------------------------------------------------------------------------
extern "C" void kernel_launch(void* const* d_in, const int* in_sizes, int n_in,
                              void* d_out, int out_size)
{
    (void)in_sizes; (void)n_in; (void)out_size;
    const float* query = (const float*)d_in[0];
    const float* kin   = (const float*)d_in[1];
    const float* vin   = (const float*)d_in[2];
    const float* Wq = (const float*)d_in[3];  const float* bq = (const float*)d_in[4];
    const float* Wk = (const float*)d_in[5];  const float* bk = (const float*)d_in[6];
    const float* Wv = (const float*)d_in[7];  const float* bv = (const float*)d_in[8];
    const float* Wg = (const float*)d_in[9];  const float* bg = (const float*)d_in[10];
    const float* Wo = (const float*)d_in[11]; const float* bo = (const float*)d_in[12];
    float* out = (float*)d_out;

    float *Qp, *Kp, *Vp, *Gp, *X2;
    cudaGetSymbolAddress((void**)&Qp, g_Q);
    cudaGetSymbolAddress((void**)&Kp, g_K);
    cudaGetSymbolAddress((void**)&Vp, g_V);
    cudaGetSymbolAddress((void**)&Gp, g_G);
    cudaGetSymbolAddress((void**)&X2, g_X2);

    const size_t ret_smem = RET_SMEM_FLOATS * sizeof(float);   // ~67 KB
    cudaFuncSetAttribute(retention_k,
                         cudaFuncAttributeMaxDynamicSharedMemorySize,
                         (int)ret_smem);

    dim3 gblk(256);
    dim3 ggrid(EMB / 128, MROWS / 128);   // (4, 32)

    gemm_k<2><<<ggrid, gblk>>>(query, Wq, bq, Qp);   // q proj + rotary
    gemm_k<3><<<ggrid, gblk>>>(kin,   Wk, bk, Kp);   // k proj + rotary + 1/8
    gemm_k<0><<<ggrid, gblk>>>(vin,   Wv, bv, Vp);   // v proj
    gemm_k<1><<<ggrid, gblk>>>(query, Wg, bg, Gp);   // gate proj + silu

    dim3 rgrid(SEQ / 64, BATCH * HEADS);  // (32, 16)
    retention_k<<<rgrid, gblk, ret_smem>>>(Qp, Kp, Vp, Gp, X2);

    gemm_k<0><<<ggrid, gblk>>>(X2, Wo, bo, out);     // output proj
}

// round 4
// speedup vs baseline: 1.5772x; 1.5772x over previous
#include <cuda_runtime.h>
#include <cuda_bf16.h>
#include <math.h>
#include <stdint.h>

#define BATCH 2
#define SEQ   2048
#define EMB   512
#define HEADS 8
#define HDIM  64
#define MROWS 4096
#define KP    1536   // 3-term split K for projections: [hi|lo|hi] x [hi|hi|lo]

// ---------------------------------------------------------------------------
// Scratch (device globals; allocation in kernel_launch is forbidden)
// ---------------------------------------------------------------------------
__device__ __align__(16) __nv_bfloat16 g_bA1[MROWS * KP];   // query split
__device__ __align__(16) __nv_bfloat16 g_bA2[MROWS * KP];   // k input split
__device__ __align__(16) __nv_bfloat16 g_bA3[MROWS * KP];   // v input split
__device__ __align__(16) __nv_bfloat16 g_bW [5 * EMB * KP]; // weights split
__device__ __align__(16) __nv_bfloat16 g_Qb [MROWS * KP];   // per-head [hi64|lo64|hi64]
__device__ __align__(16) __nv_bfloat16 g_Kb [MROWS * KP];   // per-head [hi64|hi64|lo64]
__device__ __align__(16) __nv_bfloat16 g_Vb [MROWS * 1024]; // per-head [hi64|lo64]
__device__ __align__(16) float         g_G  [MROWS * EMB];  // silu gate fp32
__device__ __align__(16) __nv_bfloat16 g_bX2[MROWS * KP];   // retention out split
__device__ __align__(16) float g_sin[SEQ * 32];
__device__ __align__(16) float g_cos[SEQ * 32];

// ---------------------------------------------------------------------------
// Helpers
// ---------------------------------------------------------------------------
__device__ __forceinline__ uint32_t smem_u32(const void* p) {
    uint32_t a;
    asm("{ .reg .u64 t; cvta.to.shared.u64 t, %1; cvt.u32.u64 %0, t; }"
        : "=r"(a) : "l"(p));
    return a;
}

__device__ __forceinline__ void mma_bf16(float* c, uint32_t a0, uint32_t a1,
                                         uint32_t a2, uint32_t a3,
                                         uint32_t b0, uint32_t b1) {
    asm volatile(
        "mma.sync.aligned.m16n8k16.row.col.f32.bf16.bf16.f32 "
        "{%0,%1,%2,%3}, {%4,%5,%6,%7}, {%8,%9}, {%0,%1,%2,%3};\n"
        : "+f"(c[0]), "+f"(c[1]), "+f"(c[2]), "+f"(c[3])
        : "r"(a0), "r"(a1), "r"(a2), "r"(a3), "r"(b0), "r"(b1));
}

#define CP16(dst, src) \
    asm volatile("cp.async.cg.shared.global [%0], [%1], 16;" \
                 :: "r"((uint32_t)(dst)), "l"(src))
#define CP_COMMIT() asm volatile("cp.async.commit_group;" ::: "memory")
#define CP_WAIT1()  asm volatile("cp.async.wait_group 1;" ::: "memory")
#define CP_WAIT0()  asm volatile("cp.async.wait_group 0;" ::: "memory")

__device__ __forceinline__ void hilo(float x, __nv_bfloat16& h, __nv_bfloat16& l) {
    h = __float2bfloat16(x);
    l = __float2bfloat16(x - __bfloat162float(h));
}
__device__ __forceinline__ uint32_t pk2(__nv_bfloat16 a, __nv_bfloat16 b) {
    uint16_t lo = *(uint16_t*)&a, hi = *(uint16_t*)&b;
    return (uint32_t)lo | ((uint32_t)hi << 16);
}

// ---------------------------------------------------------------------------
// Rotary tables
// ---------------------------------------------------------------------------
__global__ void rope_k(float* __restrict__ st, float* __restrict__ ct) {
    int i = blockIdx.x * blockDim.x + threadIdx.x;
    if (i >= SEQ * 32) return;
    int n = i >> 5, p = i & 31;
    float theta = powf(10000.f, -(float)p * (1.0f / 31.0f));
    float sv, cv;
    sincosf((float)n * theta, &sv, &cv);
    st[i] = sv;
    ct[i] = cv;
}

// ---------------------------------------------------------------------------
// fp32 -> 3-term bf16 split. Activations: [hi|lo|hi]; weights: [hi|hi|lo].
// ---------------------------------------------------------------------------
__global__ void conv_k(const float* __restrict__ src, __nv_bfloat16* __restrict__ dst,
                       int rows, int isW) {
    int idx = blockIdx.x * blockDim.x + threadIdx.x;
    if (idx >= rows * 128) return;
    int row = idx >> 7, c = (idx & 127) << 2;
    float4 v = *(const float4*)(src + (size_t)row * EMB + c);
    float x[4] = {v.x, v.y, v.z, v.w};
    __nv_bfloat16 h[4], l[4];
#pragma unroll
    for (int i = 0; i < 4; i++) hilo(x[i], h[i], l[i]);
    uint2 hp, lp;
    hp.x = pk2(h[0], h[1]); hp.y = pk2(h[2], h[3]);
    lp.x = pk2(l[0], l[1]); lp.y = pk2(l[2], l[3]);
    size_t base = (size_t)row * KP + c;
    *(uint2*)(dst + base) = hp;
    if (isW) {
        *(uint2*)(dst + base + 512)  = hp;
        *(uint2*)(dst + base + 1024) = lp;
    } else {
        *(uint2*)(dst + base + 512)  = lp;
        *(uint2*)(dst + base + 1024) = hp;
    }
}

// ---------------------------------------------------------------------------
// Projection GEMM via mma.sync: C[4096x512] = A[4096x1536] @ W[512x1536]^T
// MODE 0: fp32 out  1: silu fp32  2: rotary -> Qb split  3: rotary*0.125 -> Kb
// MODE 4: hi/lo -> Vb
// CTA 128x128, 8 warps (4m x 2n), warp tile 32x64. cp.async double buffer.
// ---------------------------------------------------------------------------
#define PJ_PITCH 144
#define PJ_TILE  (128 * PJ_PITCH)      // 18432
#define PJ_SMEM  (4 * PJ_TILE)         // 73728
#define PJ_CHUNKS (KP / 64)            // 24

template <int MODE>
__global__ void __launch_bounds__(256)
proj_k(const __nv_bfloat16* __restrict__ A, const __nv_bfloat16* __restrict__ W,
       const float* __restrict__ bias, void* __restrict__ Cout)
{
    extern __shared__ char sm[];
    const uint32_t smb = smem_u32(sm);
    const int tid = threadIdx.x;
    const int lane = tid & 31, wid = tid >> 5;
    const int g = lane >> 2, tig = lane & 3;
    const int wm = wid >> 1, wn = wid & 1;
    const int mBase = blockIdx.y * 128, nBase = blockIdx.x * 128;

    float acc[2][8][4];
#pragma unroll
    for (int a = 0; a < 2; a++)
#pragma unroll
        for (int b = 0; b < 8; b++)
#pragma unroll
            for (int c = 0; c < 4; c++) acc[a][b][c] = 0.f;

    const int crow = tid >> 1;
    const int cs0 = (tid & 1) * 4;
    const __nv_bfloat16* Arow = A + (size_t)(mBase + crow) * KP;
    const __nv_bfloat16* Wrow = W + (size_t)(nBase + crow) * KP;
    const uint32_t aDst = smb + crow * PJ_PITCH + cs0 * 16;
    const uint32_t wDst = smb + 2 * PJ_TILE + crow * PJ_PITCH + cs0 * 16;

    // prefetch chunk 0 -> buf 0
#pragma unroll
    for (int i = 0; i < 4; i++) {
        CP16(aDst + i * 16, Arow + (cs0 + i) * 8);
        CP16(wDst + i * 16, Wrow + (cs0 + i) * 8);
    }
    CP_COMMIT();

    for (int c = 0; c < PJ_CHUNKS; c++) {
        if (c + 1 < PJ_CHUNKS) {
            const uint32_t boff = (uint32_t)((c + 1) & 1) * PJ_TILE;
#pragma unroll
            for (int i = 0; i < 4; i++) {
                CP16(aDst + boff + i * 16, Arow + (c + 1) * 64 + (cs0 + i) * 8);
                CP16(wDst + boff + i * 16, Wrow + (c + 1) * 64 + (cs0 + i) * 8);
            }
            CP_COMMIT();
            CP_WAIT1();
        } else {
            CP_WAIT0();
        }
        __syncthreads();
        const char* aS = sm + (c & 1) * PJ_TILE;
        const char* wS = sm + 2 * PJ_TILE + (c & 1) * PJ_TILE;
#pragma unroll
        for (int ks = 0; ks < 4; ks++) {
            const int kb = ks * 32 + tig * 4;
            uint32_t av[2][4];
#pragma unroll
            for (int mt = 0; mt < 2; mt++) {
                const char* p = aS + (wm * 32 + mt * 16 + g) * PJ_PITCH + kb;
                av[mt][0] = *(const uint32_t*)p;
                av[mt][1] = *(const uint32_t*)(p + 8 * PJ_PITCH);
                av[mt][2] = *(const uint32_t*)(p + 16);
                av[mt][3] = *(const uint32_t*)(p + 8 * PJ_PITCH + 16);
            }
#pragma unroll
            for (int nt = 0; nt < 8; nt++) {
                const char* p = wS + (wn * 64 + nt * 8 + g) * PJ_PITCH + kb;
                uint32_t b0 = *(const uint32_t*)p;
                uint32_t b1 = *(const uint32_t*)(p + 16);
                mma_bf16(acc[0][nt], av[0][0], av[0][1], av[0][2], av[0][3], b0, b1);
                mma_bf16(acc[1][nt], av[1][0], av[1][1], av[1][2], av[1][3], b0, b1);
            }
        }
        __syncthreads();
    }

    // epilogue
#pragma unroll
    for (int mt = 0; mt < 2; mt++) {
#pragma unroll
        for (int half = 0; half < 2; half++) {
            const int row = mBase + wm * 32 + mt * 16 + g + half * 8;
            const int nseq = row & (SEQ - 1);
#pragma unroll
            for (int nt = 0; nt < 8; nt++) {
                const int col = nBase + wn * 64 + nt * 8 + tig * 2;
                float v0 = acc[mt][nt][half * 2 + 0] + __ldg(bias + col);
                float v1 = acc[mt][nt][half * 2 + 1] + __ldg(bias + col + 1);
                if (MODE == 0) {
                    *(float2*)((float*)Cout + (size_t)row * EMB + col) =
                        make_float2(v0, v1);
                } else if (MODE == 1) {
                    v0 = v0 / (1.f + expf(-v0));
                    v1 = v1 / (1.f + expf(-v1));
                    *(float2*)((float*)Cout + (size_t)row * EMB + col) =
                        make_float2(v0, v1);
                } else if (MODE == 2 || MODE == 3) {
                    const int d = col & 63, p = d >> 1, head = col >> 6;
                    const float sv = g_sin[nseq * 32 + p];
                    const float cv = g_cos[nseq * 32 + p];
                    float x = v0 * cv - v1 * sv;
                    float y = v1 * cv + v0 * sv;
                    if (MODE == 3) { x *= 0.125f; y *= 0.125f; }
                    __nv_bfloat16 h0, l0, h1, l1;
                    hilo(x, h0, l0);
                    hilo(y, h1, l1);
                    __nv_bfloat16* C = (__nv_bfloat16*)Cout;
                    const size_t base = (size_t)row * KP + head * 192 + d;
                    const uint32_t hp = pk2(h0, h1), lp = pk2(l0, l1);
                    if (MODE == 2) {   // Q: [hi|lo|hi]
                        *(uint32_t*)(C + base)       = hp;
                        *(uint32_t*)(C + base + 64)  = lp;
                        *(uint32_t*)(C + base + 128) = hp;
                    } else {           // K: [hi|hi|lo]
                        *(uint32_t*)(C + base)       = hp;
                        *(uint32_t*)(C + base + 64)  = hp;
                        *(uint32_t*)(C + base + 128) = lp;
                    }
                } else {               // MODE 4: V per-head [hi|lo]
                    __nv_bfloat16 h0, l0, h1, l1;
                    hilo(v0, h0, l0);
                    hilo(v1, h1, l1);
                    __nv_bfloat16* C = (__nv_bfloat16*)Cout;
                    const size_t base = (size_t)row * 1024 + (col >> 6) * 128 + (col & 63);
                    *(uint32_t*)(C + base)      = pk2(h0, h1);
                    *(uint32_t*)(C + base + 64) = pk2(l0, l1);
                }
            }
        }
    }
}

// ---------------------------------------------------------------------------
// Retention via mma.sync: per (b,h), 128 q-rows per CTA, loop s col tiles.
// QK 3-term (K'=192); S split hi/lo; SV 4 passes (S_hi/lo x V_hi/lo).
// GroupNorm + gate + hi/lo re-split fused in epilogue.
// ---------------------------------------------------------------------------
#define RT_QP 400   // Qs/Ks pitch bytes (192 bf16 + pad); 100 words == 4 mod 32
#define RT_VP 272   // Vt pitch (128 bf16 + pad); 68 words == 4 mod 32
#define RT_SP 528   // Ss pitch (256 bf16 + pad); 132 words == 4 mod 32
#define RT_QS  0
#define RT_KS  51200
#define RT_VH  102400
#define RT_VL  119808
#define RT_SS  137216
#define RT_TAB 204800
#define RT_SMEM 205824

__global__ void __launch_bounds__(256, 1)
ret_k(const __nv_bfloat16* __restrict__ Qb, const __nv_bfloat16* __restrict__ Kb,
      const __nv_bfloat16* __restrict__ Vb, const float* __restrict__ G,
      __nv_bfloat16* __restrict__ X2)
{
    extern __shared__ char sm[];
    float* tab = (float*)(sm + RT_TAB);
    const int tid = threadIdx.x;
    const int lane = tid & 31, wid = tid >> 5;
    const int g = lane >> 2, tig = lane & 3;
    const int rb = (int)(gridDim.x - 1 - blockIdx.x);   // heavy tiles first
    const int rowBase = rb * 128;
    const int bh = blockIdx.y;
    const int b = bh >> 3, h = bh & 7;

    const double la = -3.4657359027997265;   // log(1/32)
    const double lb = -6.2383246250395075;   // log(1/512)
    const float gamma = (float)(1.0 - exp(la + (lb - la) * ((double)h / 7.0)));
    const float lg2g = log2f(gamma);
    if (tid < 256) tab[tid] = exp2f(lg2g * (float)(tid - 128));

    // Q tile: 128 rows x 192 bf16
    {
        const __nv_bfloat16* qs = Qb + (size_t)(b * SEQ + rowBase) * KP + h * 192;
        for (int e = tid; e < 128 * 24; e += 256) {
            int r = e / 24, q = e - r * 24;
            *(uint4*)(sm + RT_QS + r * RT_QP + q * 16) =
                *(const uint4*)(qs + (size_t)r * KP + q * 8);
        }
    }

    float sacc[8][4];
#pragma unroll
    for (int i = 0; i < 8; i++)
#pragma unroll
        for (int j = 0; j < 4; j++) sacc[i][j] = 0.f;

    for (int sT = 0; sT <= rb; sT++) {
        const int colBase = sT * 128;
        __syncthreads();
        // K tile
        {
            const __nv_bfloat16* ks = Kb + (size_t)(b * SEQ + colBase) * KP + h * 192;
            for (int e = tid; e < 128 * 24; e += 256) {
                int r = e / 24, q = e - r * 24;
                *(uint4*)(sm + RT_KS + r * RT_QP + q * 16) =
                    *(const uint4*)(ks + (size_t)r * KP + q * 8);
            }
        }
        // V tile transposed into VtH / VtL
        {
            const __nv_bfloat16* vs = Vb + (size_t)(b * SEQ + colBase) * 1024 + h * 128;
            for (int e = tid; e < 128 * 32; e += 256) {
                int s = e >> 5, q = e & 31, col = q * 4;
                uint2 v = *(const uint2*)(vs + (size_t)s * 1024 + col);
                const __nv_bfloat16* pv = (const __nv_bfloat16*)&v;
                char* base = (col < 64) ? (sm + RT_VH + col * RT_VP)
                                        : (sm + RT_VL + (col - 64) * RT_VP);
#pragma unroll
                for (int i = 0; i < 4; i++)
                    *(__nv_bfloat16*)(base + i * RT_VP + s * 2) = pv[i];
            }
        }
        __syncthreads();

        // S = Q K^T  (warp = 16 rows, 16 n8 tiles, 12 k16 steps)
        float qk[16][4];
#pragma unroll
        for (int i = 0; i < 16; i++)
#pragma unroll
            for (int j = 0; j < 4; j++) qk[i][j] = 0.f;

        const char* qrow = sm + RT_QS + (wid * 16 + g) * RT_QP;
#pragma unroll
        for (int ks = 0; ks < 12; ks++) {
            const int kb = ks * 32 + tig * 4;
            uint32_t a0 = *(const uint32_t*)(qrow + kb);
            uint32_t a1 = *(const uint32_t*)(qrow + 8 * RT_QP + kb);
            uint32_t a2 = *(const uint32_t*)(qrow + kb + 16);
            uint32_t a3 = *(const uint32_t*)(qrow + 8 * RT_QP + kb + 16);
#pragma unroll
            for (int nt = 0; nt < 16; nt++) {
                const char* kp = sm + RT_KS + (nt * 8 + g) * RT_QP + kb;
                mma_bf16(qk[nt], a0, a1, a2, a3,
                         *(const uint32_t*)kp, *(const uint32_t*)(kp + 16));
            }
        }

        // decay mask + hi/lo split into Ss
        const float basefac = exp2f(lg2g * (float)(rowBase - colBase));
        const bool diag = (sT == rb);
#pragma unroll
        for (int nt = 0; nt < 16; nt++) {
            const int lj = nt * 8 + tig * 2;
#pragma unroll
            for (int half = 0; half < 2; half++) {
                const int li = wid * 16 + g + half * 8;
                const int d0 = li - lj, d1 = li - lj - 1;
                float w0 = basefac * tab[d0 + 128];
                float w1 = basefac * tab[d1 + 128];
                if (diag && d0 < 0) w0 = 0.f;
                if (diag && d1 < 0) w1 = 0.f;
                const float v0 = qk[nt][half * 2 + 0] * w0;
                const float v1 = qk[nt][half * 2 + 1] * w1;
                __nv_bfloat16 h0, l0, h1, l1;
                hilo(v0, h0, l0);
                hilo(v1, h1, l1);
                char* p = sm + RT_SS + li * RT_SP + lj * 2;
                *(uint32_t*)p         = pk2(h0, h1);
                *(uint32_t*)(p + 256) = pk2(l0, l1);
            }
        }
        __syncthreads();

        // acc += S V : 4 passes (S_hi,S_lo) x (V_hi,V_lo)
        const char* srow = sm + RT_SS + (wid * 16 + g) * RT_SP;
#pragma unroll
        for (int pass = 0; pass < 4; pass++) {
            const int aoff = (pass & 1) * 256;
            const char* vbase = (pass & 2) ? (sm + RT_VL) : (sm + RT_VH);
#pragma unroll
            for (int ks = 0; ks < 8; ks++) {
                const int kb = ks * 32 + tig * 4;
                uint32_t a0 = *(const uint32_t*)(srow + aoff + kb);
                uint32_t a1 = *(const uint32_t*)(srow + aoff + 8 * RT_SP + kb);
                uint32_t a2 = *(const uint32_t*)(srow + aoff + kb + 16);
                uint32_t a3 = *(const uint32_t*)(srow + aoff + 8 * RT_SP + kb + 16);
#pragma unroll
                for (int nt = 0; nt < 8; nt++) {
                    const char* vp = vbase + (nt * 8 + g) * RT_VP + kb;
                    mma_bf16(sacc[nt], a0, a1, a2, a3,
                             *(const uint32_t*)vp, *(const uint32_t*)(vp + 16));
                }
            }
        }
    }

    // GroupNorm over d=64 per row + gate + hi/lo store
    float s1a = 0.f, s2a = 0.f, s1b = 0.f, s2b = 0.f;
#pragma unroll
    for (int nt = 0; nt < 8; nt++) {
        s1a += sacc[nt][0] + sacc[nt][1];
        s2a += sacc[nt][0] * sacc[nt][0] + sacc[nt][1] * sacc[nt][1];
        s1b += sacc[nt][2] + sacc[nt][3];
        s2b += sacc[nt][2] * sacc[nt][2] + sacc[nt][3] * sacc[nt][3];
    }
#pragma unroll
    for (int m = 1; m <= 2; m <<= 1) {
        s1a += __shfl_xor_sync(0xffffffffu, s1a, m);
        s2a += __shfl_xor_sync(0xffffffffu, s2a, m);
        s1b += __shfl_xor_sync(0xffffffffu, s1b, m);
        s2b += __shfl_xor_sync(0xffffffffu, s2b, m);
    }
    const float meanA = s1a * (1.f / 64.f);
    const float meanB = s1b * (1.f / 64.f);
    float varA = fmaxf(s2a * (1.f / 64.f) - meanA * meanA, 0.f);
    float varB = fmaxf(s2b * (1.f / 64.f) - meanB * meanB, 0.f);
    const float invA = rsqrtf(varA + 1e-6f);
    const float invB = rsqrtf(varB + 1e-6f);

    const int mrowA = b * SEQ + rowBase + wid * 16 + g;
    const int mrowB = mrowA + 8;
#pragma unroll
    for (int nt = 0; nt < 8; nt++) {
        const int d = nt * 8 + tig * 2;
        const float2 ga = *(const float2*)(G + (size_t)mrowA * EMB + h * 64 + d);
        const float2 gb = *(const float2*)(G + (size_t)mrowB * EMB + h * 64 + d);
        float xa0 = (sacc[nt][0] - meanA) * invA * ga.x;
        float xa1 = (sacc[nt][1] - meanA) * invA * ga.y;
        float xb0 = (sacc[nt][2] - meanB) * invB * gb.x;
        float xb1 = (sacc[nt][3] - meanB) * invB * gb.y;
        __nv_bfloat16 h0, l0, h1, l1;
        hilo(xa0, h0, l0);
        hilo(xa1, h1, l1);
        {
            const size_t base = (size_t)mrowA * KP + h * 64 + d;
            const uint32_t hp = pk2(h0, h1), lp = pk2(l0, l1);
            *(uint32_t*)(X2 + base)        = hp;
            *(uint32_t*)(X2 + base + 512)  = lp;
            *(uint32_t*)(X2 + base + 1024) = hp;
        }
        hilo(xb0, h0, l0);
        hilo(xb1, h1, l1);
        {
            const size_t base = (size_t)mrowB * KP + h * 64 + d;
            const uint32_t hp = pk2(h0, h1), lp = pk2(l0, l1);
            *(uint32_t*)(X2 + base)        = hp;
            *(uint32_t*)(X2 + base + 512)  = lp;
            *(uint32_t*)(X2 + base + 1024) = hp;
        }
    }
}

// ---------------------------------------------------------------------------
// Launch
// ---------------------------------------------------------------------------
extern "C" void kernel_launch(void* const* d_in, const int* in_sizes, int n_in,
                              void* d_out, int out_size)
{
    (void)in_sizes; (void)n_in; (void)out_size;
    const float* query = (const float*)d_in[0];
    const float* kin   = (const float*)d_in[1];
    const float* vin   = (const float*)d_in[2];
    const float* Wq = (const float*)d_in[3];  const float* bq = (const float*)d_in[4];
    const float* Wk = (const float*)d_in[5];  const float* bk = (const float*)d_in[6];
    const float* Wv = (const float*)d_in[7];  const float* bv = (const float*)d_in[8];
    const float* Wg = (const float*)d_in[9];  const float* bg = (const float*)d_in[10];
    const float* Wo = (const float*)d_in[11]; const float* bo = (const float*)d_in[12];
    float* out = (float*)d_out;

    float *Gf, *sinp, *cosp;
    __nv_bfloat16 *bA1, *bA2, *bA3, *bW, *Qb, *Kb, *Vb, *bX2;
    cudaGetSymbolAddress((void**)&bA1, g_bA1);
    cudaGetSymbolAddress((void**)&bA2, g_bA2);
    cudaGetSymbolAddress((void**)&bA3, g_bA3);
    cudaGetSymbolAddress((void**)&bW,  g_bW);
    cudaGetSymbolAddress((void**)&Qb,  g_Qb);
    cudaGetSymbolAddress((void**)&Kb,  g_Kb);
    cudaGetSymbolAddress((void**)&Vb,  g_Vb);
    cudaGetSymbolAddress((void**)&Gf,  g_G);
    cudaGetSymbolAddress((void**)&bX2, g_bX2);
    cudaGetSymbolAddress((void**)&sinp, g_sin);
    cudaGetSymbolAddress((void**)&cosp, g_cos);

    cudaFuncSetAttribute(proj_k<0>, cudaFuncAttributeMaxDynamicSharedMemorySize, PJ_SMEM);
    cudaFuncSetAttribute(proj_k<1>, cudaFuncAttributeMaxDynamicSharedMemorySize, PJ_SMEM);
    cudaFuncSetAttribute(proj_k<2>, cudaFuncAttributeMaxDynamicSharedMemorySize, PJ_SMEM);
    cudaFuncSetAttribute(proj_k<3>, cudaFuncAttributeMaxDynamicSharedMemorySize, PJ_SMEM);
    cudaFuncSetAttribute(proj_k<4>, cudaFuncAttributeMaxDynamicSharedMemorySize, PJ_SMEM);
    cudaFuncSetAttribute(ret_k, cudaFuncAttributeMaxDynamicSharedMemorySize, RT_SMEM);

    rope_k<<<256, 256>>>(sinp, cosp);

    const size_t wOff = (size_t)EMB * KP;
    conv_k<<<(MROWS * 128 + 255) / 256, 256>>>(query, bA1, MROWS, 0);
    conv_k<<<(MROWS * 128 + 255) / 256, 256>>>(kin,   bA2, MROWS, 0);
    conv_k<<<(MROWS * 128 + 255) / 256, 256>>>(vin,   bA3, MROWS, 0);
    conv_k<<<(EMB * 128 + 255) / 256, 256>>>(Wq, bW + 0 * wOff, EMB, 1);
    conv_k<<<(EMB * 128 + 255) / 256, 256>>>(Wk, bW + 1 * wOff, EMB, 1);
    conv_k<<<(EMB * 128 + 255) / 256, 256>>>(Wv, bW + 2 * wOff, EMB, 1);
    conv_k<<<(EMB * 128 + 255) / 256, 256>>>(Wg, bW + 3 * wOff, EMB, 1);
    conv_k<<<(EMB * 128 + 255) / 256, 256>>>(Wo, bW + 4 * wOff, EMB, 1);

    dim3 pg(EMB / 128, MROWS / 128);   // (4, 32)
    proj_k<2><<<pg, 256, PJ_SMEM>>>(bA1, bW + 0 * wOff, bq, Qb);
    proj_k<3><<<pg, 256, PJ_SMEM>>>(bA2, bW + 1 * wOff, bk, Kb);
    proj_k<4><<<pg, 256, PJ_SMEM>>>(bA3, bW + 2 * wOff, bv, Vb);
    proj_k<1><<<pg, 256, PJ_SMEM>>>(bA1, bW + 3 * wOff, bg, Gf);

    dim3 rg(SEQ / 128, BATCH * HEADS);  // (16, 16)
    ret_k<<<rg, 256, RT_SMEM>>>(Qb, Kb, Vb, Gf, bX2);

    proj_k<0><<<pg, 256, PJ_SMEM>>>(bX2, bW + 4 * wOff, bo, out);
}

// round 6
// speedup vs baseline: 1.6477x; 1.0447x over previous
#include <cuda_runtime.h>
#include <cuda_bf16.h>
#include <math.h>
#include <stdint.h>

#define BATCH 2
#define SEQ   2048
#define EMB   512
#define HEADS 8
#define HDIM  64
#define MROWS 4096
#define KP    1536   // 3-term split K for projections: [hi|lo|hi] x [hi|hi|lo]

// ---------------------------------------------------------------------------
// Scratch (device globals; allocation in kernel_launch is forbidden)
// ---------------------------------------------------------------------------
__device__ __align__(16) __nv_bfloat16 g_bA1[MROWS * KP];   // query split
__device__ __align__(16) __nv_bfloat16 g_bA2[MROWS * KP];   // k input split
__device__ __align__(16) __nv_bfloat16 g_bA3[MROWS * KP];   // v input split
__device__ __align__(16) __nv_bfloat16 g_bW [5 * EMB * KP]; // weights split
__device__ __align__(16) __nv_bfloat16 g_Qb [MROWS * KP];   // per-head [hi64|lo64|hi64]
__device__ __align__(16) __nv_bfloat16 g_Kb [MROWS * KP];   // per-head [hi64|hi64|lo64]
__device__ __align__(16) __nv_bfloat16 g_Vb [MROWS * 1024]; // per-head [hi64|lo64]
__device__ __align__(16) float         g_G  [MROWS * EMB];  // silu gate fp32
__device__ __align__(16) __nv_bfloat16 g_bX2[MROWS * KP];   // retention out split
__device__ __align__(16) float g_sin[SEQ * 32];
__device__ __align__(16) float g_cos[SEQ * 32];

// ---------------------------------------------------------------------------
// Helpers
// ---------------------------------------------------------------------------
__device__ __forceinline__ uint32_t smem_u32(const void* p) {
    uint32_t a;
    asm("{ .reg .u64 t; cvta.to.shared.u64 t, %1; cvt.u32.u64 %0, t; }"
        : "=r"(a) : "l"(p));
    return a;
}

__device__ __forceinline__ void mma_bf16(float* c, uint32_t a0, uint32_t a1,
                                         uint32_t a2, uint32_t a3,
                                         uint32_t b0, uint32_t b1) {
    asm volatile(
        "mma.sync.aligned.m16n8k16.row.col.f32.bf16.bf16.f32 "
        "{%0,%1,%2,%3}, {%4,%5,%6,%7}, {%8,%9}, {%0,%1,%2,%3};\n"
        : "+f"(c[0]), "+f"(c[1]), "+f"(c[2]), "+f"(c[3])
        : "r"(a0), "r"(a1), "r"(a2), "r"(a3), "r"(b0), "r"(b1));
}

#define CP16(dst, src) \
    asm volatile("cp.async.cg.shared.global [%0], [%1], 16;" \
                 :: "r"((uint32_t)(dst)), "l"(src))
#define CP_COMMIT() asm volatile("cp.async.commit_group;" ::: "memory")
#define CP_WAIT1()  asm volatile("cp.async.wait_group 1;" ::: "memory")
#define CP_WAIT0()  asm volatile("cp.async.wait_group 0;" ::: "memory")

__device__ __forceinline__ void hilo(float x, __nv_bfloat16& h, __nv_bfloat16& l) {
    h = __float2bfloat16(x);
    l = __float2bfloat16(x - __bfloat162float(h));
}
__device__ __forceinline__ uint32_t pk2(__nv_bfloat16 a, __nv_bfloat16 b) {
    uint16_t lo = *(uint16_t*)&a, hi = *(uint16_t*)&b;
    return (uint32_t)lo | ((uint32_t)hi << 16);
}

// ---------------------------------------------------------------------------
// Rotary tables
// ---------------------------------------------------------------------------
__global__ void rope_k(float* __restrict__ st, float* __restrict__ ct) {
    int i = blockIdx.x * blockDim.x + threadIdx.x;
    if (i >= SEQ * 32) return;
    int n = i >> 5, p = i & 31;
    float theta = powf(10000.f, -(float)p * (1.0f / 31.0f));
    float sv, cv;
    sincosf((float)n * theta, &sv, &cv);
    st[i] = sv;
    ct[i] = cv;
}

// ---------------------------------------------------------------------------
// fp32 -> 3-term bf16 split. Activations: [hi|lo|hi]; weights: [hi|hi|lo].
// (Byte-identical layout to the round-4 conv_k; merged into 2 launches.)
// ---------------------------------------------------------------------------
__device__ __forceinline__ void split4(const float* __restrict__ src,
                                       __nv_bfloat16* __restrict__ dst,
                                       int idx, int isW) {
    int row = idx >> 7, c = (idx & 127) << 2;
    float4 v = *(const float4*)(src + (size_t)row * EMB + c);
    float x[4] = {v.x, v.y, v.z, v.w};
    __nv_bfloat16 h[4], l[4];
#pragma unroll
    for (int i = 0; i < 4; i++) hilo(x[i], h[i], l[i]);
    uint2 hp, lp;
    hp.x = pk2(h[0], h[1]); hp.y = pk2(h[2], h[3]);
    lp.x = pk2(l[0], l[1]); lp.y = pk2(l[2], l[3]);
    size_t base = (size_t)row * KP + c;
    *(uint2*)(dst + base) = hp;
    if (isW) {
        *(uint2*)(dst + base + 512)  = hp;
        *(uint2*)(dst + base + 1024) = lp;
    } else {
        *(uint2*)(dst + base + 512)  = lp;
        *(uint2*)(dst + base + 1024) = hp;
    }
}

__global__ void convA_k(const float* __restrict__ s0, const float* __restrict__ s1,
                        const float* __restrict__ s2,
                        __nv_bfloat16* __restrict__ d0, __nv_bfloat16* __restrict__ d1,
                        __nv_bfloat16* __restrict__ d2) {
    int idx = blockIdx.x * blockDim.x + threadIdx.x;
    if (idx >= MROWS * 128) return;
    const float* src; __nv_bfloat16* dst;
    if (blockIdx.y == 0)      { src = s0; dst = d0; }
    else if (blockIdx.y == 1) { src = s1; dst = d1; }
    else                      { src = s2; dst = d2; }
    split4(src, dst, idx, 0);
}

__global__ void convW_k(const float* __restrict__ s0, const float* __restrict__ s1,
                        const float* __restrict__ s2, const float* __restrict__ s3,
                        const float* __restrict__ s4, __nv_bfloat16* __restrict__ dst) {
    int idx = blockIdx.x * blockDim.x + threadIdx.x;
    if (idx >= EMB * 128) return;
    const float* src;
    switch (blockIdx.y) {
        case 0: src = s0; break;
        case 1: src = s1; break;
        case 2: src = s2; break;
        case 3: src = s3; break;
        default: src = s4; break;
    }
    split4(src, dst + (size_t)blockIdx.y * EMB * KP, idx, 1);
}

// ---------------------------------------------------------------------------
// Projection GEMM via mma.sync: C[4096x512] = A[4096x1536] @ W[512x1536]^T
// MODE 0: fp32 out  1: silu fp32  2: rotary -> Qb split  3: rotary*0.125 -> Kb
// MODE 4: hi/lo -> Vb
// CTA 128x128, 8 warps (4m x 2n), warp tile 32x64. cp.async double buffer.
// ---------------------------------------------------------------------------
#define PJ_PITCH 144
#define PJ_TILE  (128 * PJ_PITCH)      // 18432
#define PJ_SMEM  (4 * PJ_TILE)         // 73728
#define PJ_CHUNKS (KP / 64)            // 24

template <int MODE>
__global__ void __launch_bounds__(256)
proj_k(const __nv_bfloat16* __restrict__ A, const __nv_bfloat16* __restrict__ W,
       const float* __restrict__ bias, void* __restrict__ Cout)
{
    extern __shared__ char sm[];
    const uint32_t smb = smem_u32(sm);
    const int tid = threadIdx.x;
    const int lane = tid & 31, wid = tid >> 5;
    const int g = lane >> 2, tig = lane & 3;
    const int wm = wid >> 1, wn = wid & 1;
    const int mBase = blockIdx.y * 128, nBase = blockIdx.x * 128;

    float acc[2][8][4];
#pragma unroll
    for (int a = 0; a < 2; a++)
#pragma unroll
        for (int b = 0; b < 8; b++)
#pragma unroll
            for (int c = 0; c < 4; c++) acc[a][b][c] = 0.f;

    const int crow = tid >> 1;
    const int cs0 = (tid & 1) * 4;
    const __nv_bfloat16* Arow = A + (size_t)(mBase + crow) * KP;
    const __nv_bfloat16* Wrow = W + (size_t)(nBase + crow) * KP;
    const uint32_t aDst = smb + crow * PJ_PITCH + cs0 * 16;
    const uint32_t wDst = smb + 2 * PJ_TILE + crow * PJ_PITCH + cs0 * 16;

    // prefetch chunk 0 -> buf 0
#pragma unroll
    for (int i = 0; i < 4; i++) {
        CP16(aDst + i * 16, Arow + (cs0 + i) * 8);
        CP16(wDst + i * 16, Wrow + (cs0 + i) * 8);
    }
    CP_COMMIT();

    for (int c = 0; c < PJ_CHUNKS; c++) {
        if (c + 1 < PJ_CHUNKS) {
            const uint32_t boff = (uint32_t)((c + 1) & 1) * PJ_TILE;
#pragma unroll
            for (int i = 0; i < 4; i++) {
                CP16(aDst + boff + i * 16, Arow + (c + 1) * 64 + (cs0 + i) * 8);
                CP16(wDst + boff + i * 16, Wrow + (c + 1) * 64 + (cs0 + i) * 8);
            }
            CP_COMMIT();
            CP_WAIT1();
        } else {
            CP_WAIT0();
        }
        __syncthreads();
        const char* aS = sm + (c & 1) * PJ_TILE;
        const char* wS = sm + 2 * PJ_TILE + (c & 1) * PJ_TILE;
#pragma unroll
        for (int ks = 0; ks < 4; ks++) {
            const int kb = ks * 32 + tig * 4;
            uint32_t av[2][4];
#pragma unroll
            for (int mt = 0; mt < 2; mt++) {
                const char* p = aS + (wm * 32 + mt * 16 + g) * PJ_PITCH + kb;
                av[mt][0] = *(const uint32_t*)p;
                av[mt][1] = *(const uint32_t*)(p + 8 * PJ_PITCH);
                av[mt][2] = *(const uint32_t*)(p + 16);
                av[mt][3] = *(const uint32_t*)(p + 8 * PJ_PITCH + 16);
            }
#pragma unroll
            for (int nt = 0; nt < 8; nt++) {
                const char* p = wS + (wn * 64 + nt * 8 + g) * PJ_PITCH + kb;
                uint32_t b0 = *(const uint32_t*)p;
                uint32_t b1 = *(const uint32_t*)(p + 16);
                mma_bf16(acc[0][nt], av[0][0], av[0][1], av[0][2], av[0][3], b0, b1);
                mma_bf16(acc[1][nt], av[1][0], av[1][1], av[1][2], av[1][3], b0, b1);
            }
        }
        __syncthreads();
    }

    // epilogue
#pragma unroll
    for (int mt = 0; mt < 2; mt++) {
#pragma unroll
        for (int half = 0; half < 2; half++) {
            const int row = mBase + wm * 32 + mt * 16 + g + half * 8;
            const int nseq = row & (SEQ - 1);
#pragma unroll
            for (int nt = 0; nt < 8; nt++) {
                const int col = nBase + wn * 64 + nt * 8 + tig * 2;
                float v0 = acc[mt][nt][half * 2 + 0] + __ldg(bias + col);
                float v1 = acc[mt][nt][half * 2 + 1] + __ldg(bias + col + 1);
                if (MODE == 0) {
                    *(float2*)((float*)Cout + (size_t)row * EMB + col) =
                        make_float2(v0, v1);
                } else if (MODE == 1) {
                    v0 = v0 / (1.f + expf(-v0));
                    v1 = v1 / (1.f + expf(-v1));
                    *(float2*)((float*)Cout + (size_t)row * EMB + col) =
                        make_float2(v0, v1);
                } else if (MODE == 2 || MODE == 3) {
                    const int d = col & 63, p = d >> 1, head = col >> 6;
                    const float sv = g_sin[nseq * 32 + p];
                    const float cv = g_cos[nseq * 32 + p];
                    float x = v0 * cv - v1 * sv;
                    float y = v1 * cv + v0 * sv;
                    if (MODE == 3) { x *= 0.125f; y *= 0.125f; }
                    __nv_bfloat16 h0, l0, h1, l1;
                    hilo(x, h0, l0);
                    hilo(y, h1, l1);
                    __nv_bfloat16* C = (__nv_bfloat16*)Cout;
                    const size_t base = (size_t)row * KP + head * 192 + d;
                    const uint32_t hp = pk2(h0, h1), lp = pk2(l0, l1);
                    if (MODE == 2) {   // Q: [hi|lo|hi]
                        *(uint32_t*)(C + base)       = hp;
                        *(uint32_t*)(C + base + 64)  = lp;
                        *(uint32_t*)(C + base + 128) = hp;
                    } else {           // K: [hi|hi|lo]
                        *(uint32_t*)(C + base)       = hp;
                        *(uint32_t*)(C + base + 64)  = hp;
                        *(uint32_t*)(C + base + 128) = lp;
                    }
                } else {               // MODE 4: V per-head [hi|lo]
                    __nv_bfloat16 h0, l0, h1, l1;
                    hilo(v0, h0, l0);
                    hilo(v1, h1, l1);
                    __nv_bfloat16* C = (__nv_bfloat16*)Cout;
                    const size_t base = (size_t)row * 1024 + (col >> 6) * 128 + (col & 63);
                    *(uint32_t*)(C + base)      = pk2(h0, h1);
                    *(uint32_t*)(C + base + 64) = pk2(l0, l1);
                }
            }
        }
    }
}

// ---------------------------------------------------------------------------
// Retention via mma.sync: per (b,h), 128 q-rows per CTA, loop s col tiles.
// QK 3-term (K'=192); S split hi/lo; SV 3 passes (lo*lo dropped, ~2^-18).
// GroupNorm + gate + hi/lo re-split fused in epilogue.
// ---------------------------------------------------------------------------
#define RT_QP 400   // Qs/Ks pitch bytes (192 bf16 + pad); 100 words == 4 mod 32
#define RT_VP 272   // Vt pitch (128 bf16 + pad); 68 words == 4 mod 32
#define RT_SP 528   // Ss pitch (256 bf16 + pad); 132 words == 4 mod 32
#define RT_QS  0
#define RT_KS  51200
#define RT_VH  102400
#define RT_VL  119808
#define RT_SS  137216
#define RT_TAB 204800
#define RT_SMEM 205824

__global__ void __launch_bounds__(256, 1)
ret_k(const __nv_bfloat16* __restrict__ Qb, const __nv_bfloat16* __restrict__ Kb,
      const __nv_bfloat16* __restrict__ Vb, const float* __restrict__ G,
      __nv_bfloat16* __restrict__ X2)
{
    extern __shared__ char sm[];
    float* tab = (float*)(sm + RT_TAB);
    const int tid = threadIdx.x;
    const int lane = tid & 31, wid = tid >> 5;
    const int g = lane >> 2, tig = lane & 3;
    const int rb = (int)(gridDim.x - 1 - blockIdx.x);   // heavy tiles first
    const int rowBase = rb * 128;
    const int bh = blockIdx.y;
    const int b = bh >> 3, h = bh & 7;

    const double la = -3.4657359027997265;   // log(1/32)
    const double lb = -6.2383246250395075;   // log(1/512)
    const float gamma = (float)(1.0 - exp(la + (lb - la) * ((double)h / 7.0)));
    const float lg2g = log2f(gamma);
    if (tid < 256) tab[tid] = exp2f(lg2g * (float)(tid - 128));

    // Q tile: 128 rows x 192 bf16
    {
        const __nv_bfloat16* qs = Qb + (size_t)(b * SEQ + rowBase) * KP + h * 192;
        for (int e = tid; e < 128 * 24; e += 256) {
            int r = e / 24, q = e - r * 24;
            *(uint4*)(sm + RT_QS + r * RT_QP + q * 16) =
                *(const uint4*)(qs + (size_t)r * KP + q * 8);
        }
    }

    float sacc[8][4];
#pragma unroll
    for (int i = 0; i < 8; i++)
#pragma unroll
        for (int j = 0; j < 4; j++) sacc[i][j] = 0.f;

    for (int sT = 0; sT <= rb; sT++) {
        const int colBase = sT * 128;
        __syncthreads();
        // K tile
        {
            const __nv_bfloat16* ks = Kb + (size_t)(b * SEQ + colBase) * KP + h * 192;
            for (int e = tid; e < 128 * 24; e += 256) {
                int r = e / 24, q = e - r * 24;
                *(uint4*)(sm + RT_KS + r * RT_QP + q * 16) =
                    *(const uint4*)(ks + (size_t)r * KP + q * 8);
            }
        }
        // V tile transposed into VtH / VtL
        {
            const __nv_bfloat16* vs = Vb + (size_t)(b * SEQ + colBase) * 1024 + h * 128;
            for (int e = tid; e < 128 * 32; e += 256) {
                int s = e >> 5, q = e & 31, col = q * 4;
                uint2 v = *(const uint2*)(vs + (size_t)s * 1024 + col);
                const __nv_bfloat16* pv = (const __nv_bfloat16*)&v;
                char* base = (col < 64) ? (sm + RT_VH + col * RT_VP)
                                        : (sm + RT_VL + (col - 64) * RT_VP);
#pragma unroll
                for (int i = 0; i < 4; i++)
                    *(__nv_bfloat16*)(base + i * RT_VP + s * 2) = pv[i];
            }
        }
        __syncthreads();

        // S = Q K^T  (warp = 16 rows, 16 n8 tiles, 12 k16 steps)
        float qk[16][4];
#pragma unroll
        for (int i = 0; i < 16; i++)
#pragma unroll
            for (int j = 0; j < 4; j++) qk[i][j] = 0.f;

        const char* qrow = sm + RT_QS + (wid * 16 + g) * RT_QP;
#pragma unroll
        for (int ks = 0; ks < 12; ks++) {
            const int kb = ks * 32 + tig * 4;
            uint32_t a0 = *(const uint32_t*)(qrow + kb);
            uint32_t a1 = *(const uint32_t*)(qrow + 8 * RT_QP + kb);
            uint32_t a2 = *(const uint32_t*)(qrow + kb + 16);
            uint32_t a3 = *(const uint32_t*)(qrow + 8 * RT_QP + kb + 16);
#pragma unroll
            for (int nt = 0; nt < 16; nt++) {
                const char* kp = sm + RT_KS + (nt * 8 + g) * RT_QP + kb;
                mma_bf16(qk[nt], a0, a1, a2, a3,
                         *(const uint32_t*)kp, *(const uint32_t*)(kp + 16));
            }
        }

        // decay mask + hi/lo split into Ss
        const float basefac = exp2f(lg2g * (float)(rowBase - colBase));
        const bool diag = (sT == rb);
#pragma unroll
        for (int nt = 0; nt < 16; nt++) {
            const int lj = nt * 8 + tig * 2;
#pragma unroll
            for (int half = 0; half < 2; half++) {
                const int li = wid * 16 + g + half * 8;
                const int d0 = li - lj, d1 = d0 - 1;
                float w0 = basefac * tab[d0 + 128];
                float w1 = basefac * tab[d1 + 128];
                if (diag && d0 < 0) w0 = 0.f;
                if (diag && d1 < 0) w1 = 0.f;
                const float v0 = qk[nt][half * 2 + 0] * w0;
                const float v1 = qk[nt][half * 2 + 1] * w1;
                __nv_bfloat16 h0, l0, h1, l1;
                hilo(v0, h0, l0);
                hilo(v1, h1, l1);
                char* p = sm + RT_SS + li * RT_SP + lj * 2;
                *(uint32_t*)p         = pk2(h0, h1);
                *(uint32_t*)(p + 256) = pk2(l0, l1);
            }
        }
        __syncthreads();

        // acc += S V : 3 passes (S_hi*V_hi, S_lo*V_hi, S_hi*V_lo)
        const char* srow = sm + RT_SS + (wid * 16 + g) * RT_SP;
#pragma unroll
        for (int pass = 0; pass < 3; pass++) {
            const int aoff = (pass & 1) * 256;
            const char* vbase = (pass & 2) ? (sm + RT_VL) : (sm + RT_VH);
#pragma unroll
            for (int ks = 0; ks < 8; ks++) {
                const int kb = ks * 32 + tig * 4;
                uint32_t a0 = *(const uint32_t*)(srow + aoff + kb);
                uint32_t a1 = *(const uint32_t*)(srow + aoff + 8 * RT_SP + kb);
                uint32_t a2 = *(const uint32_t*)(srow + aoff + kb + 16);
                uint32_t a3 = *(const uint32_t*)(srow + aoff + 8 * RT_SP + kb + 16);
#pragma unroll
                for (int nt = 0; nt < 8; nt++) {
                    const char* vp = vbase + (nt * 8 + g) * RT_VP + kb;
                    mma_bf16(sacc[nt], a0, a1, a2, a3,
                             *(const uint32_t*)vp, *(const uint32_t*)(vp + 16));
                }
            }
        }
    }

    // GroupNorm over d=64 per row + gate + hi/lo store
    float s1a = 0.f, s2a = 0.f, s1b = 0.f, s2b = 0.f;
#pragma unroll
    for (int nt = 0; nt < 8; nt++) {
        s1a += sacc[nt][0] + sacc[nt][1];
        s2a += sacc[nt][0] * sacc[nt][0] + sacc[nt][1] * sacc[nt][1];
        s1b += sacc[nt][2] + sacc[nt][3];
        s2b += sacc[nt][2] * sacc[nt][2] + sacc[nt][3] * sacc[nt][3];
    }
#pragma unroll
    for (int m = 1; m <= 2; m <<= 1) {
        s1a += __shfl_xor_sync(0xffffffffu, s1a, m);
        s2a += __shfl_xor_sync(0xffffffffu, s2a, m);
        s1b += __shfl_xor_sync(0xffffffffu, s1b, m);
        s2b += __shfl_xor_sync(0xffffffffu, s2b, m);
    }
    const float meanA = s1a * (1.f / 64.f);
    const float meanB = s1b * (1.f / 64.f);
    float varA = fmaxf(s2a * (1.f / 64.f) - meanA * meanA, 0.f);
    float varB = fmaxf(s2b * (1.f / 64.f) - meanB * meanB, 0.f);
    const float invA = rsqrtf(varA + 1e-6f);
    const float invB = rsqrtf(varB + 1e-6f);

    const int mrowA = b * SEQ + rowBase + wid * 16 + g;
    const int mrowB = mrowA + 8;
#pragma unroll
    for (int nt = 0; nt < 8; nt++) {
        const int d = nt * 8 + tig * 2;
        const float2 ga = *(const float2*)(G + (size_t)mrowA * EMB + h * 64 + d);
        const float2 gb = *(const float2*)(G + (size_t)mrowB * EMB + h * 64 + d);
        float xa0 = (sacc[nt][0] - meanA) * invA * ga.x;
        float xa1 = (sacc[nt][1] - meanA) * invA * ga.y;
        float xb0 = (sacc[nt][2] - meanB) * invB * gb.x;
        float xb1 = (sacc[nt][3] - meanB) * invB * gb.y;
        __nv_bfloat16 h0, l0, h1, l1;
        hilo(xa0, h0, l0);
        hilo(xa1, h1, l1);
        {
            const size_t base = (size_t)mrowA * KP + h * 64 + d;
            const uint32_t hp = pk2(h0, h1), lp = pk2(l0, l1);
            *(uint32_t*)(X2 + base)        = hp;
            *(uint32_t*)(X2 + base + 512)  = lp;
            *(uint32_t*)(X2 + base + 1024) = hp;
        }
        hilo(xb0, h0, l0);
        hilo(xb1, h1, l1);
        {
            const size_t base = (size_t)mrowB * KP + h * 64 + d;
            const uint32_t hp = pk2(h0, h1), lp = pk2(l0, l1);
            *(uint32_t*)(X2 + base)        = hp;
            *(uint32_t*)(X2 + base + 512)  = lp;
            *(uint32_t*)(X2 + base + 1024) = hp;
        }
    }
}

// ---------------------------------------------------------------------------
// Launch
// ---------------------------------------------------------------------------
extern "C" void kernel_launch(void* const* d_in, const int* in_sizes, int n_in,
                              void* d_out, int out_size)
{
    (void)in_sizes; (void)n_in; (void)out_size;
    const float* query = (const float*)d_in[0];
    const float* kin   = (const float*)d_in[1];
    const float* vin   = (const float*)d_in[2];
    const float* Wq = (const float*)d_in[3];  const float* bq = (const float*)d_in[4];
    const float* Wk = (const float*)d_in[5];  const float* bk = (const float*)d_in[6];
    const float* Wv = (const float*)d_in[7];  const float* bv = (const float*)d_in[8];
    const float* Wg = (const float*)d_in[9];  const float* bg = (const float*)d_in[10];
    const float* Wo = (const float*)d_in[11]; const float* bo = (const float*)d_in[12];
    float* out = (float*)d_out;

    float *Gf, *sinp, *cosp;
    __nv_bfloat16 *bA1, *bA2, *bA3, *bW, *Qb, *Kb, *Vb, *bX2;
    cudaGetSymbolAddress((void**)&bA1, g_bA1);
    cudaGetSymbolAddress((void**)&bA2, g_bA2);
    cudaGetSymbolAddress((void**)&bA3, g_bA3);
    cudaGetSymbolAddress((void**)&bW,  g_bW);
    cudaGetSymbolAddress((void**)&Qb,  g_Qb);
    cudaGetSymbolAddress((void**)&Kb,  g_Kb);
    cudaGetSymbolAddress((void**)&Vb,  g_Vb);
    cudaGetSymbolAddress((void**)&Gf,  g_G);
    cudaGetSymbolAddress((void**)&bX2, g_bX2);
    cudaGetSymbolAddress((void**)&sinp, g_sin);
    cudaGetSymbolAddress((void**)&cosp, g_cos);

    cudaFuncSetAttribute(proj_k<0>, cudaFuncAttributeMaxDynamicSharedMemorySize, PJ_SMEM);
    cudaFuncSetAttribute(proj_k<1>, cudaFuncAttributeMaxDynamicSharedMemorySize, PJ_SMEM);
    cudaFuncSetAttribute(proj_k<2>, cudaFuncAttributeMaxDynamicSharedMemorySize, PJ_SMEM);
    cudaFuncSetAttribute(proj_k<3>, cudaFuncAttributeMaxDynamicSharedMemorySize, PJ_SMEM);
    cudaFuncSetAttribute(proj_k<4>, cudaFuncAttributeMaxDynamicSharedMemorySize, PJ_SMEM);
    cudaFuncSetAttribute(ret_k, cudaFuncAttributeMaxDynamicSharedMemorySize, RT_SMEM);

    rope_k<<<256, 256>>>(sinp, cosp);

    dim3 ca((MROWS * 128 + 255) / 256, 3);
    convA_k<<<ca, 256>>>(query, kin, vin, bA1, bA2, bA3);
    dim3 cw((EMB * 128 + 255) / 256, 5);
    convW_k<<<cw, 256>>>(Wq, Wk, Wv, Wg, Wo, bW);

    const size_t wOff = (size_t)EMB * KP;
    dim3 pg(EMB / 128, MROWS / 128);   // (4, 32)
    proj_k<2><<<pg, 256, PJ_SMEM>>>(bA1, bW + 0 * wOff, bq, Qb);
    proj_k<3><<<pg, 256, PJ_SMEM>>>(bA2, bW + 1 * wOff, bk, Kb);
    proj_k<4><<<pg, 256, PJ_SMEM>>>(bA3, bW + 2 * wOff, bv, Vb);
    proj_k<1><<<pg, 256, PJ_SMEM>>>(bA1, bW + 3 * wOff, bg, Gf);

    dim3 rg(SEQ / 128, BATCH * HEADS);  // (16, 16)
    ret_k<<<rg, 256, RT_SMEM>>>(Qb, Kb, Vb, Gf, bX2);

    proj_k<0><<<pg, 256, PJ_SMEM>>>(bX2, bW + 4 * wOff, bo, out);
}